// round 1
// baseline (speedup 1.0000x reference)
#include <cuda_runtime.h>

#define NS 64      // states
#define NE 128     // edges = 2*NS
#define MAXW 64    // max nonzeros per edge column (general fallback)

// Compacted gather tables for A = in_prob @ (s2e * mask).
// Built on-device each launch (graph-capturable, deterministic).
__device__ int   g_cnt[NE];
__device__ short g_src[NE][MAXW];
__device__ float g_wgt[NE][MAXW];

__global__ void prep_kernel(const float* __restrict__ s2e,
                            const float* __restrict__ mask) {
    int e = blockIdx.x * blockDim.x + threadIdx.x;
    if (e >= NE) return;
    int c = 0;
    for (int s = 0; s < NS; s++) {
        float w = s2e[s * NE + e] * mask[s * NE + e];
        if (w != 0.0f) {
            g_src[e][c] = (short)s;
            g_wgt[e][c] = w;
            c++;
        }
    }
    g_cnt[e] = c;
}

#define ROWS_PER_BLOCK 4
#define THREADS (ROWS_PER_BLOCK * NS)   // 256

__global__ void __launch_bounds__(THREADS)
acs_kernel(const float* __restrict__ in_prob,
           const float* __restrict__ llrs,
           const float* __restrict__ l2e,
           float* __restrict__ out_max,
           float* __restrict__ out_ind,
           int batch) {
    __shared__ float sh_prob[ROWS_PER_BLOCK][NS];
    __shared__ float sh_llr[ROWS_PER_BLOCK][2];
    __shared__ float sh_l2e[2][NE];

    const int tid = threadIdx.x;
    const long long b0 = (long long)blockIdx.x * ROWS_PER_BLOCK;

    // Stage small operands + this block's in_prob rows (coalesced 256-float load).
    ((float*)sh_l2e)[tid] = l2e[tid];                       // 256 == 2*NE
    long long gidx = b0 * NS + tid;
    if (gidx < (long long)batch * NS)
        ((float*)sh_prob)[tid] = in_prob[gidx];
    if (tid < ROWS_PER_BLOCK * 2) {
        long long li = b0 * 2 + tid;
        if (li < (long long)batch * 2)
            ((float*)sh_llr)[tid] = llrs[li];
    }
    __syncthreads();

    const int r = tid >> 6;         // batch row within block
    const int s = tid & 63;         // dest state
    const long long b = b0 + r;
    if (b >= batch) return;

    const int e0 = 2 * s;
    const int e1 = 2 * s + 1;

    // A-gather: in practice each edge column is one-hot -> 1 iteration.
    float a0 = 0.0f;
    int c0 = g_cnt[e0];
    #pragma unroll 1
    for (int j = 0; j < c0; j++)
        a0 += sh_prob[r][g_src[e0][j]] * g_wgt[e0][j];

    float a1 = 0.0f;
    int c1 = g_cnt[e1];
    #pragma unroll 1
    for (int j = 0; j < c1; j++)
        a1 += sh_prob[r][g_src[e1][j]] * g_wgt[e1][j];

    // Branch metrics: Bm[b,e] = llr0*l2e[0,e] + llr1*l2e[1,e]
    const float l0 = sh_llr[r][0];
    const float l1 = sh_llr[r][1];
    const float x0 = a0 + l0 * sh_l2e[0][e0] + l1 * sh_l2e[1][e0];
    const float x1 = a1 + l0 * sh_l2e[0][e1] + l1 * sh_l2e[1][e1];

    // Compare-select; jnp.argmax tie -> first index (0).
    const float mx  = fmaxf(x0, x1);
    const float ind = (x1 > x0) ? 1.0f : 0.0f;

    const long long o = b * NS + s;
    out_max[o] = mx;
    out_ind[o] = ind;
}

extern "C" void kernel_launch(void* const* d_in, const int* in_sizes, int n_in,
                              void* d_out, int out_size) {
    const float* in_prob = (const float*)d_in[0];   // [B, 64]
    const float* llrs    = (const float*)d_in[1];   // [B, 2]
    const float* s2e     = (const float*)d_in[2];   // [64, 128]
    const float* mask    = (const float*)d_in[3];   // [64, 128]
    const float* l2e     = (const float*)d_in[4];   // [2, 128]

    const int batch = in_sizes[0] / NS;

    float* out_max = (float*)d_out;                         // [B, 64]
    float* out_ind = (float*)d_out + (long long)batch * NS; // [B, 64] as 0.0/1.0

    prep_kernel<<<1, NE>>>(s2e, mask);

    const int blocks = (batch + ROWS_PER_BLOCK - 1) / ROWS_PER_BLOCK;
    acs_kernel<<<blocks, THREADS>>>(in_prob, llrs, l2e, out_max, out_ind, batch);
}

// round 2
// speedup vs baseline: 7.6313x; 7.6313x over previous
#include <cuda_runtime.h>

#define NS 64      // states
#define NE 128     // edges = 2*NS

// Per-edge collapsed weight of (states_to_edges * mask): each edge column is
// structurally one-hot (mask = fixed trellis transition pattern), so the
// column dot-product reduces to one weight at source tflat[e].
__device__ __align__(16) float g_w[NE];

__global__ void prep_kernel(const float* __restrict__ s2e,
                            const float* __restrict__ mask) {
    int e = threadIdx.x;
    if (e < NE) {
        float w = 0.0f;
        for (int s = 0; s < NS; s++)
            w += s2e[s * NE + e] * mask[s * NE + e];
        g_w[e] = w;
    }
}

#define ROWS_PER_WARP 4
#define THREADS 256

// lane l handles states {2l, 2l+1} of each row => edges 4l..4l+3.
// Sources tflat[4l+j] == 4*(l&15)+j  =>  one float4 load from prob per row.
__global__ void __launch_bounds__(THREADS)
acs_kernel(const float4* __restrict__ prob4,   // in_prob as [B*16] float4
           const float2* __restrict__ llrs2,   // llrs    as [B]    float2
           const float*  __restrict__ l2e,     // [2, 128]
           float2* __restrict__ outm2,         // max  as [B*32] float2
           float2* __restrict__ outi2,         // ind  as [B*32] float2
           int batch)
{
    const int lane = threadIdx.x & 31;
    const long long wid = (long long)blockIdx.x * (THREADS / 32) + (threadIdx.x >> 5);
    const long long row0 = wid * ROWS_PER_WARP;
    if (row0 >= batch) return;

    // Loop-invariant per-lane constants for edges 4l..4l+3 (L1-resident).
    const float4 w4 = ((const float4*)g_w)[lane];
    const float4 c0 = ((const float4*)l2e)[lane];          // l2e[0][4l..4l+3]
    const float4 c1 = ((const float4*)(l2e + NE))[lane];   // l2e[1][4l..4l+3]
    const int pidx = lane & 15;

    const int nr = (int)min((long long)ROWS_PER_WARP, (long long)batch - row0);

    float4 p[ROWS_PER_WARP];
    float2 L[ROWS_PER_WARP];
    #pragma unroll
    for (int r = 0; r < ROWS_PER_WARP; r++) {
        if (r < nr) {
            const long long row = row0 + r;
            p[r] = prob4[row * 16 + pidx];   // coalesced: 16 unique float4/row
            L[r] = llrs2[row];               // warp-broadcast
        }
    }

    #pragma unroll
    for (int r = 0; r < ROWS_PER_WARP; r++) {
        if (r >= nr) break;
        const long long row = row0 + r;

        // branch metrics for edges 4l..4l+3
        const float b0 = fmaf(L[r].x, c0.x, L[r].y * c1.x);
        const float b1 = fmaf(L[r].x, c0.y, L[r].y * c1.y);
        const float b2 = fmaf(L[r].x, c0.z, L[r].y * c1.z);
        const float b3 = fmaf(L[r].x, c0.w, L[r].y * c1.w);

        // path metrics (gather collapsed to register components)
        const float x0 = fmaf(p[r].x, w4.x, b0);
        const float x1 = fmaf(p[r].y, w4.y, b1);
        const float x2 = fmaf(p[r].z, w4.z, b2);
        const float x3 = fmaf(p[r].w, w4.w, b3);

        float2 mx, id;
        mx.x = fmaxf(x0, x1); id.x = (x1 > x0) ? 1.0f : 0.0f;  // argmax tie -> 0
        mx.y = fmaxf(x2, x3); id.y = (x3 > x2) ? 1.0f : 0.0f;

        outm2[row * 32 + lane] = mx;
        outi2[row * 32 + lane] = id;
    }
}

extern "C" void kernel_launch(void* const* d_in, const int* in_sizes, int n_in,
                              void* d_out, int out_size) {
    const float* in_prob = (const float*)d_in[0];   // [B, 64]
    const float* llrs    = (const float*)d_in[1];   // [B, 2]
    const float* s2e     = (const float*)d_in[2];   // [64, 128]
    const float* mask    = (const float*)d_in[3];   // [64, 128]
    const float* l2e     = (const float*)d_in[4];   // [2, 128]

    const int batch = in_sizes[0] / NS;

    float* out_max = (float*)d_out;                          // [B, 64]
    float* out_ind = (float*)d_out + (long long)batch * NS;  // [B, 64]

    prep_kernel<<<1, NE>>>(s2e, mask);

    const long long warps = ((long long)batch + ROWS_PER_WARP - 1) / ROWS_PER_WARP;
    const int blocks = (int)((warps + (THREADS / 32) - 1) / (THREADS / 32));
    acs_kernel<<<blocks, THREADS>>>((const float4*)in_prob,
                                    (const float2*)llrs,
                                    l2e,
                                    (float2*)out_max,
                                    (float2*)out_ind,
                                    batch);
}

// round 3
// speedup vs baseline: 8.1363x; 1.0662x over previous
#include <cuda_runtime.h>

#define NS 64      // states
#define NE 128     // edges = 2*NS
#define ROWS 8     // batch rows per warp iteration
#define THREADS 256

// Fixed trellis structure (from the problem's _build_matrices):
//   src(e) = tflat[e] = 2*((e/2)%32) + (e%2);  for e = 4l+j: src = 4*(l&15)+j.
// mask is the 0/1 indicator of exactly this pattern, so the column dot-product
//   w[e] = sum_s s2e[s,e]*mask[s,e]  collapses to  s2e[src(e),e]*mask[src(e),e].
// This handles arbitrary (learnable) VALUES in s2e / l2e.

__global__ void __launch_bounds__(THREADS)
acs_kernel(const float4* __restrict__ prob4,   // in_prob as [B*16] float4
           const float2* __restrict__ llrs2,   // llrs    as [B]    float2
           const float*  __restrict__ s2e,     // [64, 128]
           const float*  __restrict__ mask,    // [64, 128]
           const float4* __restrict__ l2e4,    // [2, 128] as float4 (64 total)
           float2* __restrict__ outm2,         // max as [B*32] float2
           float2* __restrict__ outi2,         // ind as [B*32] float2
           int batch)
{
    const int lane = threadIdx.x & 31;
    const long long wid = (long long)blockIdx.x * (THREADS / 32) + (threadIdx.x >> 5);
    const long long row0 = wid * ROWS;
    if (row0 >= batch) return;

    // Per-lane edge constants for edges 4l..4l+3 (tiny tables, L2/L1 resident).
    float w[4];
    #pragma unroll
    for (int j = 0; j < 4; j++) {
        const int e = 4 * lane + j;
        const int s = 4 * (lane & 15) + j;     // = src(e)
        w[j] = s2e[s * NE + e] * mask[s * NE + e];
    }
    const float4 c0 = l2e4[lane];        // l2e[0][4l..4l+3]
    const float4 c1 = l2e4[lane + 32];   // l2e[1][4l..4l+3]
    const int pidx = lane & 15;

    const int nr = (int)min((long long)ROWS, (long long)batch - row0);

    // Front-batch all loads for max MLP.
    float4 p[ROWS];
    float2 L[ROWS];
    if (nr == ROWS) {
        #pragma unroll
        for (int r = 0; r < ROWS; r++) {
            const long long row = row0 + r;
            p[r] = prob4[row * 16 + pidx];   // 16 unique float4 per row, coalesced
            L[r] = llrs2[row];               // warp-broadcast
        }
    } else {
        #pragma unroll
        for (int r = 0; r < ROWS; r++) {
            if (r < nr) {
                const long long row = row0 + r;
                p[r] = prob4[row * 16 + pidx];
                L[r] = llrs2[row];
            }
        }
    }

    #pragma unroll
    for (int r = 0; r < ROWS; r++) {
        if (r >= nr) break;
        const long long row = row0 + r;

        // branch metrics for edges 4l..4l+3
        const float b0 = fmaf(L[r].x, c0.x, L[r].y * c1.x);
        const float b1 = fmaf(L[r].x, c0.y, L[r].y * c1.y);
        const float b2 = fmaf(L[r].x, c0.z, L[r].y * c1.z);
        const float b3 = fmaf(L[r].x, c0.w, L[r].y * c1.w);

        // path metrics
        const float x0 = fmaf(p[r].x, w[0], b0);
        const float x1 = fmaf(p[r].y, w[1], b1);
        const float x2 = fmaf(p[r].z, w[2], b2);
        const float x3 = fmaf(p[r].w, w[3], b3);

        float2 mx, id;
        mx.x = fmaxf(x0, x1); id.x = (x1 > x0) ? 1.0f : 0.0f;  // argmax tie -> 0
        mx.y = fmaxf(x2, x3); id.y = (x3 > x2) ? 1.0f : 0.0f;

        outm2[row * 32 + lane] = mx;
        outi2[row * 32 + lane] = id;
    }
}

extern "C" void kernel_launch(void* const* d_in, const int* in_sizes, int n_in,
                              void* d_out, int out_size) {
    const float* in_prob = (const float*)d_in[0];   // [B, 64]
    const float* llrs    = (const float*)d_in[1];   // [B, 2]
    const float* s2e     = (const float*)d_in[2];   // [64, 128]
    const float* mask    = (const float*)d_in[3];   // [64, 128]
    const float* l2e     = (const float*)d_in[4];   // [2, 128]

    const int batch = in_sizes[0] / NS;

    float* out_max = (float*)d_out;                          // [B, 64]
    float* out_ind = (float*)d_out + (long long)batch * NS;  // [B, 64]

    const long long warps = ((long long)batch + ROWS - 1) / ROWS;
    const int blocks = (int)((warps + (THREADS / 32) - 1) / (THREADS / 32));

    acs_kernel<<<blocks, THREADS>>>((const float4*)in_prob,
                                    (const float2*)llrs,
                                    s2e, mask,
                                    (const float4*)l2e,
                                    (float2*)out_max,
                                    (float2*)out_ind,
                                    batch);
}

// round 4
// speedup vs baseline: 8.1443x; 1.0010x over previous
#include <cuda_runtime.h>

#define NS 64      // states
#define NE 128     // edges = 2*NS
#define ROWS 4     // batch rows per warp
#define THREADS 256

// Fixed trellis structure (from the problem's _build_matrices):
//   src(e) = tflat[e] = 2*((e/2)%32) + (e%2);  for e = 4l+j: src = 4*(l&15)+j.
// mask is the 0/1 indicator of exactly this pattern, so the column dot-product
//   w[e] = sum_s s2e[s,e]*mask[s,e]  collapses to  s2e[src(e),e]*mask[src(e),e].
// Handles arbitrary (learnable) VALUES in s2e / l2e.

__global__ void __launch_bounds__(THREADS)
acs_kernel(const float4* __restrict__ prob4,   // in_prob as [B*16] float4
           const float2* __restrict__ llrs2,   // llrs    as [B]    float2
           const float*  __restrict__ s2e,     // [64, 128]
           const float*  __restrict__ mask,    // [64, 128]
           const float4* __restrict__ l2e4,    // [2, 128] as float4 (64 total)
           float2* __restrict__ outm2,         // max as [B*32] float2
           float2* __restrict__ outi2,         // ind as [B*32] float2
           int batch)
{
    const int lane = threadIdx.x & 31;
    const long long wid = (long long)blockIdx.x * (THREADS / 32) + (threadIdx.x >> 5);
    const long long row0 = wid * ROWS;
    if (row0 >= batch) return;

    // Per-lane edge constants for edges 4l..4l+3 (tiny, L2-resident tables).
    float w[4];
    #pragma unroll
    for (int j = 0; j < 4; j++) {
        const int e = 4 * lane + j;
        const int s = 4 * (lane & 15) + j;     // = src(e)
        w[j] = s2e[s * NE + e] * mask[s * NE + e];
    }
    const float4 c0 = l2e4[lane];        // l2e[0][4l..4l+3]
    const float4 c1 = l2e4[lane + 32];   // l2e[1][4l..4l+3]
    const int pidx = lane & 15;

    const int nr = (int)min((long long)ROWS, (long long)batch - row0);

    // Front-batched streaming loads (no reuse -> evict-first).
    float4 p[ROWS];
    float2 L[ROWS];
    #pragma unroll
    for (int r = 0; r < ROWS; r++) {
        if (r < nr) {
            const long long row = row0 + r;
            p[r] = __ldcs(&prob4[row * 16 + pidx]);   // 16 unique float4/row, coalesced
            L[r] = __ldcs(&llrs2[row]);               // warp-broadcast
        }
    }

    #pragma unroll
    for (int r = 0; r < ROWS; r++) {
        if (r >= nr) break;
        const long long row = row0 + r;

        // branch metrics for edges 4l..4l+3
        const float b0 = fmaf(L[r].x, c0.x, L[r].y * c1.x);
        const float b1 = fmaf(L[r].x, c0.y, L[r].y * c1.y);
        const float b2 = fmaf(L[r].x, c0.z, L[r].y * c1.z);
        const float b3 = fmaf(L[r].x, c0.w, L[r].y * c1.w);

        // path metrics
        const float x0 = fmaf(p[r].x, w[0], b0);
        const float x1 = fmaf(p[r].y, w[1], b1);
        const float x2 = fmaf(p[r].z, w[2], b2);
        const float x3 = fmaf(p[r].w, w[3], b3);

        float2 mx, id;
        mx.x = fmaxf(x0, x1); id.x = (x1 > x0) ? 1.0f : 0.0f;  // argmax tie -> 0
        mx.y = fmaxf(x2, x3); id.y = (x3 > x2) ? 1.0f : 0.0f;

        __stcs(&outm2[row * 32 + lane], mx);   // streaming stores: write-once
        __stcs(&outi2[row * 32 + lane], id);
    }
}

extern "C" void kernel_launch(void* const* d_in, const int* in_sizes, int n_in,
                              void* d_out, int out_size) {
    const float* in_prob = (const float*)d_in[0];   // [B, 64]
    const float* llrs    = (const float*)d_in[1];   // [B, 2]
    const float* s2e     = (const float*)d_in[2];   // [64, 128]
    const float* mask    = (const float*)d_in[3];   // [64, 128]
    const float* l2e     = (const float*)d_in[4];   // [2, 128]

    const int batch = in_sizes[0] / NS;

    float* out_max = (float*)d_out;                          // [B, 64]
    float* out_ind = (float*)d_out + (long long)batch * NS;  // [B, 64]

    const long long warps = ((long long)batch + ROWS - 1) / ROWS;
    const int blocks = (int)((warps + (THREADS / 32) - 1) / (THREADS / 32));

    acs_kernel<<<blocks, THREADS>>>((const float4*)in_prob,
                                    (const float2*)llrs,
                                    s2e, mask,
                                    (const float4*)l2e,
                                    (float2*)out_max,
                                    (float2*)out_ind,
                                    batch);
}

// round 5
// speedup vs baseline: 8.3032x; 1.0195x over previous
#include <cuda_runtime.h>

#define NS 64      // states
#define NE 128     // edges = 2*NS
#define ROWS 4     // batch rows per warp
#define THREADS 256

// Fixed trellis structure (from the problem's _build_matrices):
//   src(e) = tflat[e] = 2*((e/2)%32) + (e%2).
// mask is the 0/1 indicator of exactly this pattern, so
//   w[e] = sum_s s2e[s,e]*mask[s,e] = s2e[src(e),e]*mask[src(e),e].
// Handles arbitrary (learnable) VALUES in s2e / l2e.

__global__ void __launch_bounds__(THREADS)
acs_kernel(const float4* __restrict__ prob4,   // in_prob as [B*16] float4
           const float2* __restrict__ llrs2,   // llrs    as [B]    float2
           const float*  __restrict__ s2e,     // [64, 128]
           const float*  __restrict__ mask,    // [64, 128]
           const float*  __restrict__ l2e,     // [2, 128]
           float2* __restrict__ outm2,         // max as [B*32] float2
           float2* __restrict__ outi2,         // ind as [B*32] float2
           int batch)
{
    __shared__ __align__(16) float sh_w[NE];        // collapsed edge weights
    __shared__ __align__(16) float sh_c[2 * NE];    // l2e rows

    const int tid  = threadIdx.x;
    const int lane = tid & 31;

    // Stage per-edge constants once per block (coalesced).
    if (tid < NE) {
        const int e = tid;
        const int s = 2 * ((e >> 1) & 31) + (e & 1);   // src(e)
        sh_w[e] = s2e[s * NE + e] * mask[s * NE + e];
    }
    sh_c[tid] = l2e[tid];                               // 256 == 2*NE
    __syncthreads();

    const long long wid = (long long)blockIdx.x * (THREADS / 32) + (tid >> 5);
    const long long row0 = wid * ROWS;
    if (row0 >= batch) return;

    // Per-lane constants for edges 4l..4l+3 (conflict-free LDS.128).
    const float4 w4 = ((const float4*)sh_w)[lane];
    const float4 c0 = ((const float4*)sh_c)[lane];
    const float4 c1 = ((const float4*)(sh_c + NE))[lane];
    const int pidx = lane & 15;

    const int nr = (int)min((long long)ROWS, (long long)batch - row0);

    // Front-batched loads for MLP.
    float4 p[ROWS];
    float2 L[ROWS];
    #pragma unroll
    for (int r = 0; r < ROWS; r++) {
        if (r < nr) {
            const long long row = row0 + r;
            p[r] = prob4[row * 16 + pidx];   // 16 unique float4/row, coalesced
            L[r] = llrs2[row];               // warp-broadcast
        }
    }

    #pragma unroll
    for (int r = 0; r < ROWS; r++) {
        if (r >= nr) break;
        const long long row = row0 + r;

        // branch metrics for edges 4l..4l+3
        const float b0 = fmaf(L[r].x, c0.x, L[r].y * c1.x);
        const float b1 = fmaf(L[r].x, c0.y, L[r].y * c1.y);
        const float b2 = fmaf(L[r].x, c0.z, L[r].y * c1.z);
        const float b3 = fmaf(L[r].x, c0.w, L[r].y * c1.w);

        // path metrics
        const float x0 = fmaf(p[r].x, w4.x, b0);
        const float x1 = fmaf(p[r].y, w4.y, b1);
        const float x2 = fmaf(p[r].z, w4.z, b2);
        const float x3 = fmaf(p[r].w, w4.w, b3);

        float2 mx, id;
        mx.x = fmaxf(x0, x1); id.x = (x1 > x0) ? 1.0f : 0.0f;  // argmax tie -> 0
        mx.y = fmaxf(x2, x3); id.y = (x3 > x2) ? 1.0f : 0.0f;

        outm2[row * 32 + lane] = mx;
        outi2[row * 32 + lane] = id;
    }
}

extern "C" void kernel_launch(void* const* d_in, const int* in_sizes, int n_in,
                              void* d_out, int out_size) {
    const float* in_prob = (const float*)d_in[0];   // [B, 64]
    const float* llrs    = (const float*)d_in[1];   // [B, 2]
    const float* s2e     = (const float*)d_in[2];   // [64, 128]
    const float* mask    = (const float*)d_in[3];   // [64, 128]
    const float* l2e     = (const float*)d_in[4];   // [2, 128]

    const int batch = in_sizes[0] / NS;

    float* out_max = (float*)d_out;                          // [B, 64]
    float* out_ind = (float*)d_out + (long long)batch * NS;  // [B, 64]

    const long long warps = ((long long)batch + ROWS - 1) / ROWS;
    const int blocks = (int)((warps + (THREADS / 32) - 1) / (THREADS / 32));

    acs_kernel<<<blocks, THREADS>>>((const float4*)in_prob,
                                    (const float2*)llrs,
                                    s2e, mask, l2e,
                                    (float2*)out_max,
                                    (float2*)out_ind,
                                    batch);
}